// round 10
// baseline (speedup 1.0000x reference)
#include <cuda_runtime.h>
#include <cuda_fp8.h>
#include <cstdint>

// argmin_k ||x_n - e_k||^2 ; N=8192, K=16384, C=256.  Filter-then-refine:
//  Pass1: e4m3 fp8 GEMM (e scaled 2^14): d_a = fma(-2^-13, dotS, xsq);
//         error sigma ~1.9 buckets of ulp(xsq~256). u16 tag = low16 of float
//         bits of d_a; per-point float-bits min via atomicMin.
//  Pass2: candidates = tags within 24 buckets of min; exact fp32 dot +
//         single-round fma(-2,dot,xsq) (reference bucketing);
//         u64 lex key (d_bits<<32)|idx -> lowest index on ties.
// Output: float32 indices.

#define NPTS    8192
#define KCODES  16384
#define CDIM    256
#define MT      128
#define NT      256
#define KCH     128                       // fp8 bytes per chunk
#define NCHUNK  (CDIM / KCH)              // 2
#define ROWB    144                       // padded smem row stride (bytes)
#define A_STAGE (MT * ROWB)               // 18432
#define B_STAGE (NT * ROWB)               // 36864
#define STAGE_B (A_STAGE + B_STAGE)       // 55296
#define SMEM_BYTES (2 * STAGE_B)          // 110592
#define TAG_STRIDE 264                    // u16 per staged tag row (256 + 8 pad)
#define WINDOW  24
#define MAXCAND 192

__device__ float              g_xsq[NPTS];
__device__ unsigned long long g_key[NPTS];
__device__ unsigned int       g_dmin[NPTS];
__device__ unsigned char      g_A[NPTS * CDIM];              // 2 MB fp8
__device__ unsigned char      g_B[(size_t)KCODES * CDIM];    // 4 MB fp8
__device__ unsigned short     g_tags[(size_t)NPTS * KCODES]; // 256 MB

#define CP_ASYNC16(dst, src) \
    asm volatile("cp.async.cg.shared.global [%0], [%1], 16;" :: "r"(dst), "l"(src) : "memory")

__device__ __forceinline__ uint32_t smem_u32(const void* p) {
    uint32_t a;
    asm("{ .reg .u64 t; cvta.to.shared.u64 t, %1; cvt.u32.u64 %0, t; }" : "=r"(a) : "l"(p));
    return a;
}
__device__ __forceinline__ void mma16832_f8(float* c, const uint32_t* a, const uint32_t* b) {
    asm volatile(
        "mma.sync.aligned.m16n8k32.row.col.f32.e4m3.e4m3.f32 "
        "{%0,%1,%2,%3}, {%4,%5,%6,%7}, {%8,%9}, {%0,%1,%2,%3};"
        : "+f"(c[0]), "+f"(c[1]), "+f"(c[2]), "+f"(c[3])
        : "r"(a[0]), "r"(a[1]), "r"(a[2]), "r"(a[3]), "r"(b[0]), "r"(b[1]));
}

// ---------------------------------------------------------------- small kernels
__global__ void init_kernel() {
    int n = blockIdx.x * blockDim.x + threadIdx.x;
    if (n < NPTS) { g_key[n] = 0xFFFFFFFFFFFFFFFFULL; g_dmin[n] = 0xFFFFFFFFu; }
}

__global__ void xsq_kernel(const float* __restrict__ x) {
    int n = blockIdx.x * blockDim.x + threadIdx.x;
    if (n >= NPTS) return;
    const float* p = x + (size_t)(n >> 12) * 1048576 + (n & 4095);
    float s = 0.0f;
#pragma unroll 8
    for (int c = 0; c < CDIM; c++) {
        float v = p[(size_t)c * 4096];
        s = __fadd_rn(s, __fmul_rn(v, v));
    }
    g_xsq[n] = s;
}

// x -> fp8 with 32x32 transpose
__global__ void xcvt_kernel(const float* __restrict__ x) {
    __shared__ float sX[32][33];
    int n0 = blockIdx.x * 32, c0 = blockIdx.y * 32;
    int tx = threadIdx.x, ty = threadIdx.y;          // (32, 8)
    int b = n0 >> 12, hw0 = n0 & 4095;
#pragma unroll
    for (int q = 0; q < 4; q++) {
        int c = c0 + ty + 8 * q;
        sX[ty + 8 * q][tx] = x[(size_t)b * 1048576 + (size_t)c * 4096 + hw0 + tx];
    }
    __syncthreads();
#pragma unroll
    for (int q = 0; q < 4; q++) {
        int nl = ty + 8 * q;
        g_A[(size_t)(n0 + nl) * CDIM + c0 + tx] =
            (unsigned char)__nv_cvt_float_to_fp8(sX[tx][nl], __NV_SATFINITE, __NV_E4M3);
    }
}

// codebook -> fp8, scaled 2^14 (exact)
__global__ void ecvt_kernel(const float* __restrict__ cb) {
    int k = blockIdx.x, c = threadIdx.x;
    g_B[(size_t)k * CDIM + c] =
        (unsigned char)__nv_cvt_float_to_fp8(cb[(size_t)k * CDIM + c] * 16384.0f,
                                             __NV_SATFINITE, __NV_E4M3);
}

// ---------------------------------------------------------------- pass 1 GEMM (fp8)
__global__ __launch_bounds__(512, 1)
void vq_mma_kernel() {
    extern __shared__ unsigned char sm[];
    const uint32_t sb = smem_u32(sm);

    const int tid = threadIdx.x;
    const int wid = tid >> 5, lane = tid & 31;
    const int g = lane >> 2, tig = lane & 3;
    const int wm = wid >> 2, wn = wid & 3;           // 4x4 warps, warp tile 32x64
    const int m0 = blockIdx.x * MT;
    const int n0 = blockIdx.y * NT;

    float acc[2][8][4];
#pragma unroll
    for (int mt = 0; mt < 2; mt++)
#pragma unroll
        for (int nt = 0; nt < 8; nt++)
#pragma unroll
            for (int i = 0; i < 4; i++) acc[mt][nt][i] = 0.0f;

    auto load_chunk = [&](int c) {
        const int s = c & 1;
        const int kb = c * KCH;
        const uint32_t ab = sb + (uint32_t)(s * STAGE_B);
        const uint32_t bb = ab + A_STAGE;
#pragma unroll
        for (int i = 0; i < 2; i++) {                // A: 1024 x 16B
            int u = tid + i * 512;
            int r = u >> 3, j = u & 7;
            CP_ASYNC16(ab + r * ROWB + j * 16,
                       g_A + (size_t)(m0 + r) * CDIM + kb + j * 16);
        }
#pragma unroll
        for (int i = 0; i < 4; i++) {                // B: 2048 x 16B
            int u = tid + i * 512;
            int r = u >> 3, j = u & 7;
            CP_ASYNC16(bb + r * ROWB + j * 16,
                       g_B + (size_t)(n0 + r) * CDIM + kb + j * 16);
        }
        asm volatile("cp.async.commit_group;" ::: "memory");
    };

    load_chunk(0);

#pragma unroll 1
    for (int c = 0; c < NCHUNK; c++) {
        if (c + 1 < NCHUNK) {
            load_chunk(c + 1);
            asm volatile("cp.async.wait_group 1;" ::: "memory");
        } else {
            asm volatile("cp.async.wait_group 0;" ::: "memory");
        }
        __syncthreads();

        const unsigned char* aS = sm + (c & 1) * STAGE_B;
        const unsigned char* bS = aS + A_STAGE;

#pragma unroll
        for (int ks = 0; ks < 4; ks++) {             // 4 x k32 per 128B chunk
            const int kb = ks * 32;
            uint32_t rb[8][2];
#pragma unroll
            for (int nt = 0; nt < 8; nt++) {
                const unsigned char* p = bS + (wn * 64 + nt * 8 + g) * ROWB + kb + 4 * tig;
                rb[nt][0] = *(const uint32_t*)p;
                rb[nt][1] = *(const uint32_t*)(p + 16);
            }
#pragma unroll
            for (int mt = 0; mt < 2; mt++) {
                const unsigned char* p = aS + (wm * 32 + mt * 16 + g) * ROWB + kb + 4 * tig;
                uint32_t ra[4];
                ra[0] = *(const uint32_t*)p;
                ra[1] = *(const uint32_t*)(p + 8 * ROWB);
                ra[2] = *(const uint32_t*)(p + 16);
                ra[3] = *(const uint32_t*)(p + 8 * ROWB + 16);
#pragma unroll
                for (int nt = 0; nt < 8; nt++)
                    mma16832_f8(acc[mt][nt], ra, rb[nt]);
            }
        }
        __syncthreads();
    }

    // ---- epilogue: stage tags in smem (conflict-free pad), burst to gmem ----
    const float NEG2P13 = -1.220703125e-4f;          // -2^-13
    unsigned short* sTag = (unsigned short*)sm;      // [128][TAG_STRIDE]

#pragma unroll
    for (int mt = 0; mt < 2; mt++) {
#pragma unroll
        for (int h2 = 0; h2 < 2; h2++) {
            const int rloc = wm * 32 + mt * 16 + g + h2 * 8;
            const float xsq = g_xsq[m0 + rloc];
            uint32_t mn = 0xFFFFFFFFu;
#pragma unroll
            for (int nt = 0; nt < 8; nt++) {
                float d0 = __fmaf_rn(NEG2P13, acc[mt][nt][h2 * 2 + 0], xsq);
                float d1 = __fmaf_rn(NEG2P13, acc[mt][nt][h2 * 2 + 1], xsq);
                uint32_t b0 = __float_as_uint(d0), b1 = __float_as_uint(d1);
                if (b0 < mn) mn = b0;
                if (b1 < mn) mn = b1;
                *(uint32_t*)(sTag + rloc * TAG_STRIDE + wn * 64 + nt * 8 + 2 * tig) =
                    (b0 & 0xFFFFu) | (b1 << 16);
            }
            uint32_t o1 = __shfl_xor_sync(0xFFFFFFFFu, mn, 1);
            if (o1 < mn) mn = o1;
            uint32_t o2 = __shfl_xor_sync(0xFFFFFFFFu, mn, 2);
            if (o2 < mn) mn = o2;
            if (tig == 0) atomicMin(&g_dmin[m0 + rloc], mn);
        }
    }
    __syncthreads();

    // coalesced burst: 128 rows x 512 B
#pragma unroll
    for (int i = 0; i < 8; i++) {
        int u = tid + i * 512;
        int r = u >> 5, j = u & 31;                  // 32 uint4 per row
        uint4 v = *(const uint4*)(sTag + r * TAG_STRIDE + j * 8);
        *(uint4*)(g_tags + (size_t)(m0 + r) * KCODES + n0 + j * 8) = v;
    }
}

// ---------------------------------------------------------------- pass 2 scan+refine
__global__ __launch_bounds__(256, 4)
void scan_refine_kernel(const float* __restrict__ x, const float* __restrict__ cb) {
    __shared__ int   s_cnt;
    __shared__ int   s_list[MAXCAND];
    __shared__ float sx[CDIM];

    const int n = blockIdx.x;
    const int tid = threadIdx.x;
    const int wid = tid >> 5, lane = tid & 31;
    const unsigned short tmin = (unsigned short)(g_dmin[n] & 0xFFFFu);

    if (tid == 0) s_cnt = 0;
    sx[tid] = x[(size_t)(n >> 12) * 1048576 + (size_t)tid * 4096 + (n & 4095)];
    __syncthreads();

    const uint4* tags = (const uint4*)(g_tags + (size_t)n * KCODES);
#pragma unroll
    for (int i = 0; i < 8; i++) {
        const int u = tid + i * 256;
        uint4 v = tags[u];
        uint32_t w[4] = {v.x, v.y, v.z, v.w};
        const int kb = u * 8;
#pragma unroll
        for (int j = 0; j < 4; j++) {
            unsigned short t0 = (unsigned short)(w[j] & 0xFFFFu);
            unsigned short t1 = (unsigned short)(w[j] >> 16);
            if ((unsigned short)(t0 - tmin) <= WINDOW) {
                int p = atomicAdd(&s_cnt, 1);
                if (p < MAXCAND) s_list[p] = kb + 2 * j;
            }
            if ((unsigned short)(t1 - tmin) <= WINDOW) {
                int p = atomicAdd(&s_cnt, 1);
                if (p < MAXCAND) s_list[p] = kb + 2 * j + 1;
            }
        }
    }
    __syncthreads();
    const int cnt = min(s_cnt, MAXCAND);
    const float xsq = g_xsq[n];

    // one warp per candidate
    for (int e = wid; e < cnt; e += 8) {
        const int k = s_list[e];
        const float* ep = cb + (size_t)k * CDIM;
        float p = 0.0f;
#pragma unroll
        for (int j = 0; j < 8; j++)
            p = __fmaf_rn(sx[j * 32 + lane], ep[j * 32 + lane], p);
#pragma unroll
        for (int o = 16; o; o >>= 1) p += __shfl_xor_sync(0xFFFFFFFFu, p, o);
        if (lane == 0) {
            float d = __fmaf_rn(-2.0f, p, xsq);          // reference bucketing
            unsigned long long key =
                ((unsigned long long)__float_as_uint(d) << 32) | (unsigned)k;
            atomicMin(&g_key[n], key);
        }
    }
}

// ---------------------------------------------------------------- extract
__global__ void extract_kernel(float* __restrict__ out) {
    int n = blockIdx.x * blockDim.x + threadIdx.x;
    if (n < NPTS) out[n] = (float)(unsigned)(g_key[n] & 0xFFFFFFFFULL);
}

extern "C" void kernel_launch(void* const* d_in, const int* in_sizes, int n_in,
                              void* d_out, int out_size) {
    const float* x  = (const float*)d_in[0];
    const float* cb = (const float*)d_in[1];
    if (n_in >= 2 && in_sizes[0] == KCODES * CDIM) {
        const float* t = x; x = cb; cb = t;
    }
    float* out = (float*)d_out;

    static int smem_set = 0;
    if (!smem_set) {
        cudaFuncSetAttribute(vq_mma_kernel, cudaFuncAttributeMaxDynamicSharedMemorySize,
                             SMEM_BYTES);
        smem_set = 1;
    }

    init_kernel<<<NPTS / 256, 256>>>();
    xsq_kernel<<<NPTS / 256, 256>>>(x);
    {
        dim3 g(NPTS / 32, CDIM / 32), b(32, 8);
        xcvt_kernel<<<g, b>>>(x);
    }
    ecvt_kernel<<<KCODES, CDIM>>>(cb);
    {
        dim3 g(NPTS / MT, KCODES / NT);              // (64, 64)
        vq_mma_kernel<<<g, 512, SMEM_BYTES>>>();
    }
    scan_refine_kernel<<<NPTS, 256>>>(x, cb);
    extract_kernel<<<NPTS / 256, 256>>>(out);
}